// round 6
// baseline (speedup 1.0000x reference)
#include <cuda_runtime.h>

// CRF broadcast-add: out[b,l,i,j] = emission[b,l,j] + transition[i,j]
// B=32, L=512, T=64  ->  BL=16384 tiles, tile = 64x64 fp32 = 1024 float4
//
// Thread t (of 256) owns float4 positions p = t + 256k (k=0..3) in each tile.
// p%16 == t%16 -> one emission float4 per tile per thread; the 4 transition
// float4s are tile-invariant and live in registers.
//
// R4 change (resubmitted after infra failure): software prefetch of the next
// tile's emission float4 BEFORE the current tile's stores, decoupling the
// DRAM read latency (~577cyc) from the store stream. R3 measured DRAM at 59%
// with load-wait -> store-burst serialization per iteration.

constexpr int Bc = 32;
constexpr int Lc = 512;
constexpr int Tc = 64;
constexpr int BL = Bc * Lc;                 // 16384
constexpr int TILE_F4 = (Tc * Tc) / 4;      // 1024
constexpr int EM_F4_PER_TILE = Tc / 4;      // 16
constexpr int THREADS = 256;
constexpr int F4_PER_THREAD = TILE_F4 / THREADS;  // 4

__global__ void __launch_bounds__(THREADS, 8)
crf_broadcast_add(const float4* __restrict__ em4,
                  const float4* __restrict__ tr4,
                  float4* __restrict__ out4)
{
    const int t  = threadIdx.x;
    const int j4 = t & (EM_F4_PER_TILE - 1);   // t % 16

    // Tile-invariant transition rows -> registers, loaded once.
    float4 tr[F4_PER_THREAD];
#pragma unroll
    for (int k = 0; k < F4_PER_THREAD; ++k)
        tr[k] = __ldg(&tr4[t + THREADS * k]);

    const int stride = gridDim.x;
    int bl = blockIdx.x;
    if (bl >= BL) return;

    // Prime the pipeline: first emission load in flight.
    float4 e = __ldg(&em4[(size_t)bl * EM_F4_PER_TILE + j4]);

    while (true) {
        const int bln = bl + stride;

        // Prefetch NEXT tile's emission before this tile's stores, so the
        // read stream runs one iteration ahead of the write stream.
        float4 en;
        const bool more = (bln < BL);
        if (more)
            en = __ldg(&em4[(size_t)bln * EM_F4_PER_TILE + j4]);

        float4* __restrict__ o = out4 + (size_t)bl * TILE_F4 + t;
#pragma unroll
        for (int k = 0; k < F4_PER_THREAD; ++k) {
            float4 v;
            v.x = e.x + tr[k].x;
            v.y = e.y + tr[k].y;
            v.z = e.z + tr[k].z;
            v.w = e.w + tr[k].w;
            __stcs(o + THREADS * k, v);   // streaming: evict-first
        }

        if (!more) break;
        e  = en;
        bl = bln;
    }
}

extern "C" void kernel_launch(void* const* d_in, const int* in_sizes, int n_in,
                              void* d_out, int out_size)
{
    const float4* em4 = (const float4*)d_in[0];   // emission [B, L, T] fp32
    const float4* tr4 = (const float4*)d_in[1];   // transition [T, T] fp32
    float4* out4      = (float4*)d_out;           // [B, L, T, T] fp32

    const int grid = 152 * 8;   // GB300: 152 SMs, 8 CTAs/SM resident
    crf_broadcast_add<<<grid, THREADS>>>(em4, tr4, out4);
}